// round 5
// baseline (speedup 1.0000x reference)
#include <cuda_runtime.h>
#include <math.h>
#include <stdint.h>

#define K_CODES   8192
#define CDIM      256
#define NQ        32768
#define OUT_ELEMS 8388608

#define MT 128                 // M per CTA
#define NT 256                 // N per CTA tile
#define KC 32                  // K per chunk
#define PAD 36                 // smem row stride (floats)
#define N_TILES (K_CODES/NT)   // 32
#define K_CHUNKS (CDIM/KC)     // 8
#define THREADS 512

// smem float offsets
#define AHI_F 0
#define ALO_F 4608             // 128*36
#define BHI_F 9216
#define BLO_F 18432            // 9216 + 256*36
#define STAGE_F 27648
#define SMEM_BYTES (2 * STAGE_F * 4)   // 221184

__device__ float  g_ahi[(size_t)NQ * CDIM];      // k-permuted
__device__ float  g_alo[(size_t)NQ * CDIM];      // k-permuted
__device__ float  g_bhi[(size_t)K_CODES * CDIM]; // k-permuted
__device__ float  g_blo[(size_t)K_CODES * CDIM]; // k-permuted
__device__ float  g_cn [(size_t)K_CODES * CDIM]; // exact, natural order
__device__ float2 g_topv[NQ];
__device__ int2   g_topi[NQ];
__device__ int    g_idx[NQ];
__device__ double g_acc;

// within-8 k permutation: pos = 2*(k&3) + ((k>>2)&1)
__device__ __forceinline__ int kperm(int k) {
    return (k & ~7) | (((k & 3) << 1) | ((k >> 2) & 1));
}

// ---------------------------------------------------------------------------
__device__ __forceinline__ void cp16(uint32_t dst, const void* src) {
    asm volatile("cp.async.cg.shared.global [%0], [%1], 16;" :: "r"(dst), "l"(src));
}
#define CP_COMMIT() asm volatile("cp.async.commit_group;" ::: "memory")
#define CP_WAIT0()  asm volatile("cp.async.wait_group 0;" ::: "memory")

__device__ __forceinline__ uint32_t smem_u32(const void* p) {
    uint32_t a;
    asm("{ .reg .u64 t; cvta.to.shared.u64 t, %1; cvt.u32.u64 %0, t; }"
        : "=r"(a) : "l"(p));
    return a;
}

#define MMA_TF32(d, a, b) \
    asm volatile("mma.sync.aligned.m16n8k8.row.col.f32.tf32.tf32.f32 " \
        "{%0,%1,%2,%3}, {%4,%5,%6,%7}, {%8,%9}, {%0,%1,%2,%3};" \
        : "+f"((d)[0]), "+f"((d)[1]), "+f"((d)[2]), "+f"((d)[3]) \
        : "r"((a)[0]), "r"((a)[1]), "r"((a)[2]), "r"((a)[3]), \
          "r"((b)[0]), "r"((b)[1]))

__device__ __forceinline__ void tf32_split(float x, float& hi, float& lo) {
    uint32_t h;
    asm("cvt.rna.tf32.f32 %0, %1;" : "=r"(h) : "f"(x));
    hi = __uint_as_float(h);
    float r = x - hi;
    uint32_t l;
    asm("cvt.rna.tf32.f32 %0, %1;" : "=r"(l) : "f"(r));
    lo = __uint_as_float(l);
}

__device__ __forceinline__ bool better(float v, int i, float V, int I) {
    return (v > V) || (v == V && i < I);
}
__device__ __forceinline__ void top2_ins(float v, int i,
                                         float& v1, int& i1, float& v2, int& i2) {
    if (better(v, i, v1, i1)) { v2 = v1; i2 = i1; v1 = v; i1 = i; }
    else if (better(v, i, v2, i2)) { v2 = v; i2 = i; }
}

// ---------------------------------------------------------------------------
__global__ void zero_acc_kernel() { g_acc = 0.0; }

// Transpose z [B,C,H,W] -> A [n=b*1024+hw][C] (k-permuted), tf32 hi/lo split.
__global__ void split_z_kernel(const float* __restrict__ z) {
    __shared__ float th[32][33], tl[32][33];
    int tid = threadIdx.x;
    int hw0 = blockIdx.x * 32, c0 = blockIdx.y * 32, b = blockIdx.z;
#pragma unroll
    for (int i = 0; i < 4; i++) {
        int e = tid + i * 256;
        int cc = e >> 5, hh = e & 31;
        float x = z[(size_t)b * 262144 + (size_t)(c0 + cc) * 1024 + hw0 + hh];
        float h, l;
        tf32_split(x, h, l);
        th[cc][hh] = h;
        tl[cc][hh] = l;
    }
    __syncthreads();
#pragma unroll
    for (int i = 0; i < 4; i++) {
        int e = tid + i * 256;
        int hh = e >> 5, cc = e & 31;
        size_t o = (size_t)(b * 1024 + hw0 + hh) * CDIM + kperm(c0 + cc);
        g_ahi[o] = th[cc][hh];
        g_alo[o] = tl[cc][hh];
    }
}

// Normalize codebook rows; store exact cn (natural) + tf32 hi/lo (k-permuted).
__global__ void norm_split_codebook(const float* __restrict__ E) {
    int row  = blockIdx.x * 8 + (threadIdx.x >> 5);
    int lane = threadIdx.x & 31;
    const float4* r4 = (const float4*)(E + (size_t)row * CDIM);
    float4 v0 = r4[lane];
    float4 v1 = r4[lane + 32];
    float ss = v0.x*v0.x + v0.y*v0.y + v0.z*v0.z + v0.w*v0.w
             + v1.x*v1.x + v1.y*v1.y + v1.z*v1.z + v1.w*v1.w;
#pragma unroll
    for (int off = 16; off; off >>= 1)
        ss += __shfl_xor_sync(0xffffffffu, ss, off);
    float s = 1.0f / fmaxf(sqrtf(ss), 1e-12f);
    float xs[8] = {v0.x*s, v0.y*s, v0.z*s, v0.w*s, v1.x*s, v1.y*s, v1.z*s, v1.w*s};
    float4* oc = (float4*)(g_cn + (size_t)row * CDIM);
    oc[lane]      = make_float4(xs[0], xs[1], xs[2], xs[3]);
    oc[lane + 32] = make_float4(xs[4], xs[5], xs[6], xs[7]);
    float* oh = g_bhi + (size_t)row * CDIM;
    float* ol = g_blo + (size_t)row * CDIM;
#pragma unroll
    for (int j = 0; j < 8; j++) {
        int k = (j < 4) ? (lane * 4 + j) : (128 + lane * 4 + j - 4);
        float h, l;
        tf32_split(xs[j], h, l);
        int p = kperm(k);
        oh[p] = h;
        ol[p] = l;
    }
}

// ---------------------------------------------------------------------------
__device__ __forceinline__ void load_chunk(uint32_t sb_addr, int tid,
                                           int mBlk, int nt, int ct) {
    int co = ct * KC;
    const float* Ah = g_ahi + (size_t)mBlk * CDIM + co;
    const float* Al = g_alo + (size_t)mBlk * CDIM + co;
    const float* Bh = g_bhi + (size_t)nt * NT * CDIM + co;
    const float* Bl = g_blo + (size_t)nt * NT * CDIM + co;
#pragma unroll
    for (int i = 0; i < 2; i++) {
        int f = tid + i * THREADS;
        int r = f >> 3, c4 = (f & 7) << 2;
        uint32_t so = (uint32_t)(r * PAD + c4) * 4;
        cp16(sb_addr + AHI_F * 4 + so, Ah + (size_t)r * CDIM + c4);
        cp16(sb_addr + ALO_F * 4 + so, Al + (size_t)r * CDIM + c4);
    }
#pragma unroll
    for (int i = 0; i < 4; i++) {
        int f = tid + i * THREADS;
        int r = f >> 3, c4 = (f & 7) << 2;
        uint32_t so = (uint32_t)(r * PAD + c4) * 4;
        cp16(sb_addr + BHI_F * 4 + so, Bh + (size_t)r * CDIM + c4);
        cp16(sb_addr + BLO_F * 4 + so, Bl + (size_t)r * CDIM + c4);
    }
}

// ---------------------------------------------------------------------------
// HMMA tf32 3-pass GEMM + streaming per-row top-2. 16 warps, 32x64 warp tiles.
__global__ __launch_bounds__(THREADS, 1)
void vq_mma_kernel() {
    extern __shared__ float smem[];
    uint32_t smem_b = smem_u32(smem);
    int tid = threadIdx.x;
    int wid = tid >> 5, lane = tid & 31;
    int gid = lane >> 2, tig = lane & 3;
    int wm = wid >> 2, wn = wid & 3;     // 4x4 warp grid: 32-row x 64-col tiles
    int mBlk = blockIdx.x * MT;

    // epilogue scratch lives in STAGE 1 (free during epilogue)
    float2* scr_v = (float2*)(smem + STAGE_F);          // 128*4 float2
    int2*   scr_i = (int2*)(smem + STAGE_F + 1024);

    float r1v = -INFINITY, r2v = -INFINITY;
    int   r1i = 0x7fffffff, r2i = 0x7fffffff;

    load_chunk(smem_b, tid, mBlk, 0, 0);
    CP_COMMIT();

#pragma unroll 1
    for (int nt = 0; nt < N_TILES; nt++) {
        float acc[2][8][4];
#pragma unroll
        for (int mf = 0; mf < 2; mf++)
#pragma unroll
            for (int nf = 0; nf < 8; nf++)
#pragma unroll
                for (int q = 0; q < 4; q++) acc[mf][nf][q] = 0.0f;

#pragma unroll 1
        for (int ct = 0; ct < K_CHUNKS; ct++) {
            int it = nt * K_CHUNKS + ct;
            int sb = it & 1;
            CP_WAIT0();
            __syncthreads();
            if (ct != K_CHUNKS - 1) {
                load_chunk(smem_b + (sb ^ 1) * STAGE_F * 4, tid, mBlk, nt, ct + 1);
                CP_COMMIT();
            }
            const float* S = smem + sb * STAGE_F;
            const float* SaH = S + AHI_F;
            const float* SaL = S + ALO_F;
            const float* SbH = S + BHI_F;
            const float* SbL = S + BLO_F;
#pragma unroll
            for (int k8 = 0; k8 < 4; k8++) {
                int kb = k8 * 8 + 2 * tig;
                uint32_t ah[2][4];
                {
#pragma unroll
                    for (int mf = 0; mf < 2; mf++) {
                        const float* p = SaH + (wm*32 + mf*16 + gid) * PAD + kb;
                        float2 f1 = *(const float2*)(p);
                        float2 f2 = *(const float2*)(p + 8 * PAD);
                        ah[mf][0] = __float_as_uint(f1.x);
                        ah[mf][1] = __float_as_uint(f2.x);
                        ah[mf][2] = __float_as_uint(f1.y);
                        ah[mf][3] = __float_as_uint(f2.y);
                    }
                }
                {
                    uint32_t bh[8][2];
#pragma unroll
                    for (int nf = 0; nf < 8; nf++) {
                        float2 f = *(const float2*)(SbH + (wn*64 + nf*8 + gid) * PAD + kb);
                        bh[nf][0] = __float_as_uint(f.x);
                        bh[nf][1] = __float_as_uint(f.y);
                    }
#pragma unroll
                    for (int mf = 0; mf < 2; mf++)
#pragma unroll
                        for (int nf = 0; nf < 8; nf++)
                            MMA_TF32(acc[mf][nf], ah[mf], bh[nf]);
                    // a_lo x b_hi (reuse bh)
                    uint32_t al[2][4];
#pragma unroll
                    for (int mf = 0; mf < 2; mf++) {
                        const float* p = SaL + (wm*32 + mf*16 + gid) * PAD + kb;
                        float2 f1 = *(const float2*)(p);
                        float2 f2 = *(const float2*)(p + 8 * PAD);
                        al[mf][0] = __float_as_uint(f1.x);
                        al[mf][1] = __float_as_uint(f2.x);
                        al[mf][2] = __float_as_uint(f1.y);
                        al[mf][3] = __float_as_uint(f2.y);
                    }
#pragma unroll
                    for (int mf = 0; mf < 2; mf++)
#pragma unroll
                        for (int nf = 0; nf < 8; nf++)
                            MMA_TF32(acc[mf][nf], al[mf], bh[nf]);
                }
                // a_hi x b_lo (reuse ah)
                {
                    uint32_t bl[8][2];
#pragma unroll
                    for (int nf = 0; nf < 8; nf++) {
                        float2 f = *(const float2*)(SbL + (wn*64 + nf*8 + gid) * PAD + kb);
                        bl[nf][0] = __float_as_uint(f.x);
                        bl[nf][1] = __float_as_uint(f.y);
                    }
#pragma unroll
                    for (int mf = 0; mf < 2; mf++)
#pragma unroll
                        for (int nf = 0; nf < 8; nf++)
                            MMA_TF32(acc[mf][nf], ah[mf], bl[nf]);
                }
            }
        }

        // prefetch next nt's chunk 0 into stage 0 before the epilogue
        if (nt != N_TILES - 1) {
            load_chunk(smem_b, tid, mBlk, nt + 1, 0);
            CP_COMMIT();
        }
        __syncthreads();   // all warps done reading stage1 before scratch reuse

        // ---- per-ntile top-2 epilogue (scratch in stage1) ----
        int ntbase = nt * NT;
#pragma unroll
        for (int mf = 0; mf < 2; mf++) {
#pragma unroll
            for (int half = 0; half < 2; half++) {
                float v1 = -INFINITY, v2 = -INFINITY;
                int   i1 = 0x7fffffff, i2 = 0x7fffffff;
#pragma unroll
                for (int nf = 0; nf < 8; nf++) {
#pragma unroll
                    for (int p = 0; p < 2; p++) {
                        float v = acc[mf][nf][half * 2 + p];
                        int col = ntbase + wn * 64 + nf * 8 + 2 * tig + p;
                        top2_ins(v, col, v1, i1, v2, i2);
                    }
                }
#pragma unroll
                for (int off = 1; off <= 2; off <<= 1) {
                    float ov1 = __shfl_xor_sync(0xffffffffu, v1, off);
                    float ov2 = __shfl_xor_sync(0xffffffffu, v2, off);
                    int   oi1 = __shfl_xor_sync(0xffffffffu, i1, off);
                    int   oi2 = __shfl_xor_sync(0xffffffffu, i2, off);
                    top2_ins(ov1, oi1, v1, i1, v2, i2);
                    top2_ins(ov2, oi2, v1, i1, v2, i2);
                }
                if (tig == 0) {
                    int rl = wm * 32 + mf * 16 + half * 8 + gid;
                    scr_v[rl * 4 + wn] = make_float2(v1, v2);
                    scr_i[rl * 4 + wn] = make_int2(i1, i2);
                }
            }
        }
        __syncthreads();
        if (tid < 128) {
#pragma unroll
            for (int w = 0; w < 4; w++) {
                float2 vv = scr_v[tid * 4 + w];
                int2   ii = scr_i[tid * 4 + w];
                top2_ins(vv.x, ii.x, r1v, r1i, r2v, r2i);
                top2_ins(vv.y, ii.y, r1v, r1i, r2v, r2i);
            }
        }
        __syncthreads();
    }

    if (tid < 128) {
        g_topv[mBlk + tid] = make_float2(r1v, r2v);
        g_topi[mBlk + tid] = make_int2(r1i, r2i);
    }
}

// ---------------------------------------------------------------------------
// Rescore ambiguous rows (top-2 gap < eps) in exact fp32; write indices.
__global__ void fixup_kernel(const float* __restrict__ z,
                             float* __restrict__ idx_out_f) {
    int n = blockIdx.x * 256 + threadIdx.x;
    float2 tv = g_topv[n];
    int2   ti = g_topi[n];
    int ix = ti.x;
    if (tv.x - tv.y < 1e-3f) {
        int b = n >> 10, hw = n & 1023;
        const float* zr = z + (size_t)b * 262144 + hw;
        const float* c1 = g_cn + (size_t)ti.x * CDIM;
        const float* c2 = g_cn + (size_t)ti.y * CDIM;
        float d1 = 0.0f, d2 = 0.0f;
        for (int c = 0; c < CDIM; c++) {
            float zv = zr[(size_t)c * 1024];
            d1 = fmaf(zv, c1[c], d1);
            d2 = fmaf(zv, c2[c], d2);
        }
        if (better(d2, ti.y, d1, ti.x)) ix = ti.y;
    }
    g_idx[n] = ix;
    idx_out_f[n] = (float)ix;
}

// ---------------------------------------------------------------------------
__global__ void gather_loss_kernel(const float* __restrict__ z,
                                   const float* __restrict__ E,
                                   float* __restrict__ out) {
    int gid = blockIdx.x * 256 + threadIdx.x;
    int b  = gid >> 18;
    int r  = gid & 262143;
    int c  = r >> 10;
    int hw = r & 1023;
    int n  = (b << 10) + hw;
    int k  = g_idx[n];
    float q  = E[(size_t)k * CDIM + c];
    float zv = z[gid];
    float d  = q - zv;
    out[gid] = zv + d;
    float d2 = d * d;
#pragma unroll
    for (int off = 16; off; off >>= 1)
        d2 += __shfl_xor_sync(0xffffffffu, d2, off);
    __shared__ float ws[8];
    int warp = threadIdx.x >> 5;
    int lane = threadIdx.x & 31;
    if (lane == 0) ws[warp] = d2;
    __syncthreads();
    if (warp == 0) {
        float s = (lane < 8) ? ws[lane] : 0.0f;
#pragma unroll
        for (int off = 4; off; off >>= 1)
            s += __shfl_xor_sync(0xffffffffu, s, off);
        if (lane == 0) atomicAdd(&g_acc, (double)s);
    }
}

// ---------------------------------------------------------------------------
__global__ void finalize_kernel(float* __restrict__ out) {
    double m = g_acc / (double)OUT_ELEMS;
    out[OUT_ELEMS] = (float)(0.25 * m + m);
}

// ---------------------------------------------------------------------------
extern "C" void kernel_launch(void* const* d_in, const int* in_sizes, int n_in,
                              void* d_out, int out_size) {
    const float* z = (const float*)d_in[0];
    const float* E = (const float*)d_in[1];
    float* out = (float*)d_out;

    cudaFuncSetAttribute(vq_mma_kernel,
                         cudaFuncAttributeMaxDynamicSharedMemorySize, SMEM_BYTES);

    zero_acc_kernel<<<1, 1>>>();
    split_z_kernel<<<dim3(32, 8, 32), 256>>>(z);
    norm_split_codebook<<<K_CODES / 8, 256>>>(E);
    vq_mma_kernel<<<NQ / MT, THREADS, SMEM_BYTES>>>();
    fixup_kernel<<<NQ / 256, 256>>>(z, out + OUT_ELEMS + 1);
    gather_loss_kernel<<<OUT_ELEMS / 256, 256>>>(z, E, out);
    finalize_kernel<<<1, 1>>>(out);
}